// round 10
// baseline (speedup 1.0000x reference)
#include <cuda_runtime.h>
#include <cuda_bf16.h>
#include <cstdint>

#define N_PTS 8192
#define DIM 64
#define BM 128
#define NT (N_PTS / BM)            // 64 tiles per side
#define NPAIR (NT * (NT + 1) / 2)  // 2080 tile pairs
#define NTHREADS 256
#define TILE_B 16384               // 128 rows x 64 bf16 (128B rows)
#define NQ 4                       // partial quarters per tile side
#define GRID 304                   // persistent CTAs: 2 per SM x 152 SMs
#define BUF_B (4 * TILE_B + 4096)  // 4 tiles + 256 float4 metadata

// ---- scratch (device globals; all writes idempotent, replay-safe) ----
__device__ __align__(16) __nv_bfloat16 g_xhi[N_PTS * DIM];
__device__ __align__(16) __nv_bfloat16 g_xlo[N_PTS * DIM];
__device__ __align__(16) float4 g_meta[N_PTS];   // (sq, ru, lab_bits, 0)
__device__ float g_pse[NQ * NT * N_PTS];
__device__ float g_psl[NQ * NT * N_PTS];
__device__ int   g_pct[NQ * NT * N_PTS];
__device__ float g_rowloss[N_PTS];

__device__ __forceinline__ uint32_t smem_u32(const void* p) {
    uint32_t a;
    asm("{ .reg .u64 t; cvta.to.shared.u64 t, %1; cvt.u32.u64 %0, t; }" : "=r"(a) : "l"(p));
    return a;
}
__device__ __forceinline__ float fast_sqrt(float x) {
    float r; asm("sqrt.approx.f32 %0, %1;" : "=f"(r) : "f"(x)); return r;
}
__device__ __forceinline__ float fast_rcp(float x) {
    float r; asm("rcp.approx.f32 %0, %1;" : "=f"(r) : "f"(x)); return r;
}
__device__ __forceinline__ void ldsm4(uint32_t* r, uint32_t addr) {
    asm volatile("ldmatrix.sync.aligned.m8n8.x4.shared.b16 {%0,%1,%2,%3}, [%4];"
                 : "=r"(r[0]), "=r"(r[1]), "=r"(r[2]), "=r"(r[3]) : "r"(addr));
}
__device__ __forceinline__ void mma_bf16(float* d, const uint32_t* a,
                                         uint32_t b0, uint32_t b1) {
    asm("mma.sync.aligned.m16n8k16.row.col.f32.bf16.bf16.f32 "
        "{%0,%1,%2,%3}, {%4,%5,%6,%7}, {%8,%9}, {%0,%1,%2,%3};"
        : "+f"(d[0]), "+f"(d[1]), "+f"(d[2]), "+f"(d[3])
        : "r"(a[0]), "r"(a[1]), "r"(a[2]), "r"(a[3]), "r"(b0), "r"(b1));
}
__device__ __forceinline__ void cp16(uint32_t dst, const void* src) {
    asm volatile("cp.async.cg.shared.global [%0], [%1], 16;" :: "r"(dst), "l"(src));
}
#define CP_COMMIT() asm volatile("cp.async.commit_group;" ::: "memory")
#define CP_WAIT0()  asm volatile("cp.async.wait_group 0;" ::: "memory")

__device__ __forceinline__ void decode_pair(int b, int& ti, int& tj) {
    int t = (int)floorf((129.0f - sqrtf(16641.0f - 8.0f * (float)b)) * 0.5f);
    if (t < 0) t = 0;
    if (t > NT - 1) t = NT - 1;
    while (t > 0 && b < t * (129 - t) / 2) t--;
    while (b >= (t + 1) * (128 - t) / 2) t++;
    ti = t;
    tj = t + (b - t * (129 - t) / 2);
}

// ---- prep ----
__global__ void prep_kernel(const float* __restrict__ pts,
                            const long long* __restrict__ labs) {
    int i = blockIdx.x * blockDim.x + threadIdx.x;
    if (i >= N_PTS) return;
    float s = 0.f;
#pragma unroll
    for (int q = 0; q < DIM; q++) {
        float x = pts[i * DIM + q];
        s = fmaf(x, x, s);
        __nv_bfloat16 hi = __float2bfloat16(x);
        __nv_bfloat16 lo = __float2bfloat16(x - __bfloat162float(hi));
        g_xhi[i * DIM + q] = hi;
        g_xlo[i * DIM + q] = lo;
    }
    float4 m;
    m.x = s;
    m.y = 1.0f / (1.0f - s);
    m.z = __int_as_float((int)labs[i]);
    m.w = 0.f;
    g_meta[i] = m;
}

// ---- async fetch of one pair's tiles + metadata into smem ----
__device__ __forceinline__ void prefetch_pair(uint32_t dbuf, int i0, int j0, int tid) {
    const uint4* HI = (const uint4*)g_xhi;
    const uint4* LO = (const uint4*)g_xlo;
#pragma unroll
    for (int it = 0; it < 16; it++) {
        int idx = tid + it * NTHREADS;              // 0..4095
        int tile = idx >> 10;                       // 0:Ah 1:Al 2:Bh 3:Bl
        int cidx = idx & 1023;
        int row = cidx >> 3, q = cidx & 7;
        int base = (tile & 2) ? j0 : i0;
        const uint4* src = (tile & 1) ? LO : HI;
        uint32_t off = (uint32_t)(row * 128) + (uint32_t)((q ^ (row & 7)) << 4);
        cp16(dbuf + tile * TILE_B + off, &src[(base + row) * 8 + q]);
    }
    // 0..127: i rows, 128..255: j cols
    int g = ((tid >> 7) ? j0 : i0) + (tid & 127);
    cp16(dbuf + 4 * TILE_B + tid * 16, &g_meta[g]);
}

// ---- one 128x64 half: GEMM (term-major) + dual-side epilogue ----
template <bool DIAG>
__device__ __forceinline__ void compute_half(uint32_t dbuf, const char* dbufp,
                                             int ti, int tj, int i0, int j0,
                                             int lane, int wr, int ncb, int q) {
    int mr = wr * 32;
    int t8 = lane >> 3, rs = lane & 7;

    float d[2][4][4];
#pragma unroll
    for (int mf = 0; mf < 2; mf++)
#pragma unroll
        for (int nb = 0; nb < 4; nb++)
#pragma unroll
            for (int k = 0; k < 4; k++) d[mf][nb][k] = 0.f;

#pragma unroll
    for (int ks = 0; ks < 4; ks++) {
        uint32_t ah[2][4], al[2][4], bh[2][4], bl[2][4];
#pragma unroll
        for (int mf = 0; mf < 2; mf++) {
            int rowA = mr + mf * 16 + (t8 & 1) * 8 + rs;
            int ch = ks * 2 + (t8 >> 1);
            uint32_t sw = (uint32_t)(rowA * 128) + (uint32_t)((ch ^ (rowA & 7)) << 4);
            ldsm4(ah[mf], dbuf + 0 * TILE_B + sw);
            ldsm4(al[mf], dbuf + 1 * TILE_B + sw);
        }
#pragma unroll
        for (int nbp = 0; nbp < 2; nbp++) {
            int rowB = ncb + nbp * 16 + (t8 >> 1) * 8 + rs;
            int ch = ks * 2 + (t8 & 1);
            uint32_t sw = (uint32_t)(rowB * 128) + (uint32_t)((ch ^ (rowB & 7)) << 4);
            ldsm4(bh[nbp], dbuf + 2 * TILE_B + sw);
            ldsm4(bl[nbp], dbuf + 3 * TILE_B + sw);
        }
        // term-major: 8 distinct accumulators between any reuse
#pragma unroll
        for (int mf = 0; mf < 2; mf++)
#pragma unroll
            for (int nbp = 0; nbp < 2; nbp++)
#pragma unroll
                for (int nbi = 0; nbi < 2; nbi++)
                    mma_bf16(d[mf][nbp * 2 + nbi], ah[mf],
                             bh[nbp][2 * nbi], bh[nbp][2 * nbi + 1]);
#pragma unroll
        for (int mf = 0; mf < 2; mf++)
#pragma unroll
            for (int nbp = 0; nbp < 2; nbp++)
#pragma unroll
                for (int nbi = 0; nbi < 2; nbi++)
                    mma_bf16(d[mf][nbp * 2 + nbi], ah[mf],
                             bl[nbp][2 * nbi], bl[nbp][2 * nbi + 1]);
#pragma unroll
        for (int mf = 0; mf < 2; mf++)
#pragma unroll
            for (int nbp = 0; nbp < 2; nbp++)
#pragma unroll
                for (int nbi = 0; nbi < 2; nbi++)
                    mma_bf16(d[mf][nbp * 2 + nbi], al[mf],
                             bh[nbp][2 * nbi], bh[nbp][2 * nbi + 1]);
    }

    const float4* meta_i = (const float4*)(dbufp + 4 * TILE_B);
    const float4* meta_j = meta_i + 128;

    float sqr[4], rur[4];
    int labr[4], rloc4[4];
#pragma unroll
    for (int f = 0; f < 4; f++) {
        int rloc = mr + (f >> 1) * 16 + (f & 1) * 8 + (lane >> 2);
        rloc4[f] = rloc;
        float4 m = meta_i[rloc];
        sqr[f] = m.x; rur[f] = 2.0f * m.y; labr[f] = __float_as_int(m.z);
    }
    float rse[4], rpr[4];
    int rct[4];
#pragma unroll
    for (int f = 0; f < 4; f++) { rse[f] = 0.f; rpr[f] = 1.f; rct[f] = 0; }

#pragma unroll
    for (int nb = 0; nb < 4; nb++) {
#pragma unroll
        for (int ki = 0; ki < 2; ki++) {
            int cloc = ncb + nb * 8 + (lane & 3) * 2 + ki;
            float4 mj = meta_j[cloc];
            int lj = __float_as_int(mj.z);
            float cse = 0.f, cpr = 1.f;
            int cct = 0;
#pragma unroll
            for (int f = 0; f < 4; f++) {
                float dot = d[f >> 1][nb][(f & 1) * 2 + ki];
                float sqd = fmaxf(fmaf(-2.0f, dot, sqr[f] + mj.x), 0.f);
                float z = fmaf(sqd * rur[f], mj.y, 1.0f);
                z = fmaxf(z, 1.0f + 1e-7f);
                float s = fast_sqrt(fmaf(z, z, -1.0f));
                float rv = fast_rcp(z + s);
                bool pos;
                float rve;
                if (DIAG) {
                    bool offd = (rloc4[f] != cloc);
                    pos = offd && (labr[f] == lj);
                    rve = offd ? rv : 0.f;
                } else {
                    pos = (labr[f] == lj);
                    rve = rv;
                }
                float rvp = pos ? rv : 1.f;
                rse[f] += rve; rpr[f] *= rvp; rct[f] += pos;
                cse += rve; cpr *= rvp; cct += pos;
            }
            // col-side inline reduce over lane>>2 (skip on diagonal pairs)
            if (!DIAG) {
                float csl = __log2f(cpr);
                cse += __shfl_xor_sync(0xffffffffu, cse, 4);
                csl += __shfl_xor_sync(0xffffffffu, csl, 4);
                cct += __shfl_xor_sync(0xffffffffu, cct, 4);
                cse += __shfl_xor_sync(0xffffffffu, cse, 8);
                csl += __shfl_xor_sync(0xffffffffu, csl, 8);
                cct += __shfl_xor_sync(0xffffffffu, cct, 8);
                cse += __shfl_xor_sync(0xffffffffu, cse, 16);
                csl += __shfl_xor_sync(0xffffffffu, csl, 16);
                cct += __shfl_xor_sync(0xffffffffu, cct, 16);
                if (lane < 4) {
                    int cstore = ncb + nb * 8 + lane * 2 + ki;
                    int slot = (ti * NQ + wr) * N_PTS + (j0 + cstore);
                    g_pse[slot] = cse;
                    g_psl[slot] = csl * 0.69314718055994531f;
                    g_pct[slot] = cct;
                }
            }
        }
    }

    // row-side: reduce over lane&3; products <=8 factors (>=6e-21), no renorm
#pragma unroll
    for (int f = 0; f < 4; f++) {
        float se = rse[f];
        float sl = __log2f(rpr[f]);
        int ct = rct[f];
        se += __shfl_xor_sync(0xffffffffu, se, 1);
        sl += __shfl_xor_sync(0xffffffffu, sl, 1);
        ct += __shfl_xor_sync(0xffffffffu, ct, 1);
        se += __shfl_xor_sync(0xffffffffu, se, 2);
        sl += __shfl_xor_sync(0xffffffffu, sl, 2);
        ct += __shfl_xor_sync(0xffffffffu, ct, 2);
        if ((lane & 3) == 0) {
            int slot = (tj * NQ + q) * N_PTS + (i0 + rloc4[f]);
            g_pse[slot] = se;
            g_psl[slot] = sl * 0.69314718055994531f;
            g_pct[slot] = ct;
        }
    }
}

// ---- main: persistent, 2 CTAs/SM, cross-CTA overlap ----
__global__ __launch_bounds__(NTHREADS, 2)
void main_kernel() {
    extern __shared__ __align__(16) char dsm_raw[];
    uint32_t dsm0 = smem_u32(dsm_raw);
    uint32_t dsm = (dsm0 + 127u) & ~127u;
    char* dsmp = dsm_raw + (dsm - dsm0);

    int tid = threadIdx.x;
    int w = tid >> 5, lane = tid & 31;
    int wr = w & 3, wc = w >> 2;                    // 8 warps: 4 row x 2 col

    for (int p = blockIdx.x; p < NPAIR; p += GRID) {
        int ti, tj;
        decode_pair(p, ti, tj);
        int i0 = ti * BM, j0 = tj * BM;

        prefetch_pair(dsm, i0, j0, tid);
        CP_COMMIT();
        CP_WAIT0();
        __syncthreads();

        if (ti == tj) {
#pragma unroll
            for (int pass = 0; pass < 2; pass++) {
                int ncb = pass * 64 + wc * 32;
                compute_half<true>(dsm, dsmp, ti, tj, i0, j0, lane, wr, ncb,
                                   pass * 2 + wc);
            }
        } else {
#pragma unroll
            for (int pass = 0; pass < 2; pass++) {
                int ncb = pass * 64 + wc * 32;
                compute_half<false>(dsm, dsmp, ti, tj, i0, j0, lane, wr, ncb,
                                    pass * 2 + wc);
            }
        }
        __syncthreads();                            // protect buffer reuse
    }
}

__global__ void rowred_kernel() {
    int i = blockIdx.x * blockDim.x + threadIdx.x;
    if (i >= N_PTS) return;
    float se = 0.f, sl = 0.f;
    int ct = 0;
#pragma unroll 8
    for (int t = 0; t < NQ * NT; t++) {
        se += g_pse[t * N_PTS + i];
        sl += g_psl[t * N_PTS + i];
        ct += g_pct[t * N_PTS + i];
    }
    float logA = __logf(fmaxf(se, 1e-30f));
    float P = (float)(ct > 0 ? ct : 1);
    g_rowloss[i] = logA - sl / P;
}

__global__ void final_kernel(float* __restrict__ out) {
    __shared__ float red[256];
    int t = threadIdx.x;
    float acc = 0.f;
#pragma unroll
    for (int it = 0; it < N_PTS / 256; it++)
        acc += g_rowloss[t + it * 256];
    red[t] = acc;
    __syncthreads();
    for (int s = 128; s > 0; s >>= 1) {
        if (t < s) red[t] += red[t + s];
        __syncthreads();
    }
    if (t == 0) out[0] = red[0];
}

extern "C" void kernel_launch(void* const* d_in, const int* in_sizes, int n_in,
                              void* d_out, int out_size) {
    const float* pts = (const float*)d_in[0];
    const long long* labs = (const long long*)d_in[1];
    cudaFuncSetAttribute(main_kernel, cudaFuncAttributeMaxDynamicSharedMemorySize,
                         BUF_B + 128);
    prep_kernel<<<N_PTS / 256, 256>>>(pts, labs);
    main_kernel<<<GRID, NTHREADS, BUF_B + 128>>>();
    rowred_kernel<<<N_PTS / 256, 256>>>();
    final_kernel<<<1, 256>>>((float*)d_out);
}

// round 12
// speedup vs baseline: 1.2418x; 1.2418x over previous
#include <cuda_runtime.h>
#include <cuda_bf16.h>
#include <cstdint>

#define N_PTS 8192
#define DIM 64
#define BM 128
#define NT (N_PTS / BM)            // 64 tiles per side
#define NPAIR (NT * (NT + 1) / 2)  // 2080 tile pairs
#define NTHREADS 512
#define TILE_B 16384               // 128 rows x 64 bf16 (128B rows)
#define NQ 4                       // partial quarters per tile side
#define GRID 152                   // persistent CTAs
#define BUF_B (4 * TILE_B + 4096)  // 4 tiles + 256 float4 metadata

// ---- scratch (device globals; all writes idempotent, replay-safe) ----
__device__ __align__(16) __nv_bfloat16 g_xhi[N_PTS * DIM];
__device__ __align__(16) __nv_bfloat16 g_xlo[N_PTS * DIM];
__device__ __align__(16) float4 g_meta[N_PTS];   // (sq, ru, lab_bits, 0)
__device__ float g_pse[NQ * NT * N_PTS];
__device__ float g_psl[NQ * NT * N_PTS];
__device__ int   g_pct[NQ * NT * N_PTS];
__device__ float g_rowloss[N_PTS];

__device__ __forceinline__ uint32_t smem_u32(const void* p) {
    uint32_t a;
    asm("{ .reg .u64 t; cvta.to.shared.u64 t, %1; cvt.u32.u64 %0, t; }" : "=r"(a) : "l"(p));
    return a;
}
__device__ __forceinline__ float fast_sqrt(float x) {
    float r; asm("sqrt.approx.f32 %0, %1;" : "=f"(r) : "f"(x)); return r;
}
__device__ __forceinline__ void ldsm4(uint32_t* r, uint32_t addr) {
    asm volatile("ldmatrix.sync.aligned.m8n8.x4.shared.b16 {%0,%1,%2,%3}, [%4];"
                 : "=r"(r[0]), "=r"(r[1]), "=r"(r[2]), "=r"(r[3]) : "r"(addr));
}
__device__ __forceinline__ void mma_bf16(float* d, const uint32_t* a,
                                         uint32_t b0, uint32_t b1) {
    asm("mma.sync.aligned.m16n8k16.row.col.f32.bf16.bf16.f32 "
        "{%0,%1,%2,%3}, {%4,%5,%6,%7}, {%8,%9}, {%0,%1,%2,%3};"
        : "+f"(d[0]), "+f"(d[1]), "+f"(d[2]), "+f"(d[3])
        : "r"(a[0]), "r"(a[1]), "r"(a[2]), "r"(a[3]), "r"(b0), "r"(b1));
}
__device__ __forceinline__ void cp16(uint32_t dst, const void* src) {
    asm volatile("cp.async.cg.shared.global [%0], [%1], 16;" :: "r"(dst), "l"(src));
}
#define CP_COMMIT() asm volatile("cp.async.commit_group;" ::: "memory")
#define CP_WAIT1()  asm volatile("cp.async.wait_group 1;" ::: "memory")

__device__ __forceinline__ void decode_pair(int b, int& ti, int& tj) {
    int t = (int)floorf((129.0f - sqrtf(16641.0f - 8.0f * (float)b)) * 0.5f);
    if (t < 0) t = 0;
    if (t > NT - 1) t = NT - 1;
    while (t > 0 && b < t * (129 - t) / 2) t--;
    while (b >= (t + 1) * (128 - t) / 2) t++;
    ti = t;
    tj = t + (b - t * (129 - t) / 2);
}

// ---- prep ----
__global__ void prep_kernel(const float* __restrict__ pts,
                            const long long* __restrict__ labs) {
    int i = blockIdx.x * blockDim.x + threadIdx.x;
    if (i >= N_PTS) return;
    float s = 0.f;
#pragma unroll
    for (int q = 0; q < DIM; q++) {
        float x = pts[i * DIM + q];
        s = fmaf(x, x, s);
        __nv_bfloat16 hi = __float2bfloat16(x);
        __nv_bfloat16 lo = __float2bfloat16(x - __bfloat162float(hi));
        g_xhi[i * DIM + q] = hi;
        g_xlo[i * DIM + q] = lo;
    }
    float4 m;
    m.x = s;
    m.y = 1.0f / (1.0f - s);
    m.z = __int_as_float((int)labs[i]);
    m.w = 0.f;
    g_meta[i] = m;
}

// ---- async prefetch of one pair's tiles + metadata into a smem buffer ----
__device__ __forceinline__ void prefetch_pair(uint32_t dbuf, int i0, int j0, int tid) {
    const uint4* HI = (const uint4*)g_xhi;
    const uint4* LO = (const uint4*)g_xlo;
#pragma unroll
    for (int it = 0; it < 8; it++) {
        int idx = tid + it * NTHREADS;              // 0..4095
        int tile = idx >> 10;                       // 0:Ah 1:Al 2:Bh 3:Bl
        int cidx = idx & 1023;
        int row = cidx >> 3, q = cidx & 7;
        int base = (tile & 2) ? j0 : i0;
        const uint4* src = (tile & 1) ? LO : HI;
        uint32_t off = (uint32_t)(row * 128) + (uint32_t)((q ^ (row & 7)) << 4);
        cp16(dbuf + tile * TILE_B + off, &src[(base + row) * 8 + q]);
    }
    if (tid < 256) {                                // 0..127: i rows, 128..255: j cols
        int g = ((tid >> 7) ? j0 : i0) + (tid & 127);
        cp16(dbuf + 4 * TILE_B + tid * 16, &g_meta[g]);
    }
}

// ---- one pair: GEMM (term-major) + dual-side epilogue, single-MUFU rv ----
template <bool DIAG>
__device__ __forceinline__ void compute_pair(uint32_t dbuf, const char* dbufp,
                                             int ti, int tj, int i0, int j0,
                                             int lane, int wr, int wc) {
    int mr = wr * 32, nc = wc * 32;
    int t8 = lane >> 3, rs = lane & 7;

    float d[2][4][4];
#pragma unroll
    for (int mf = 0; mf < 2; mf++)
#pragma unroll
        for (int nb = 0; nb < 4; nb++)
#pragma unroll
            for (int k = 0; k < 4; k++) d[mf][nb][k] = 0.f;

#pragma unroll
    for (int ks = 0; ks < 4; ks++) {
        uint32_t ah[2][4], al[2][4], bh[2][4], bl[2][4];
#pragma unroll
        for (int mf = 0; mf < 2; mf++) {
            int rowA = mr + mf * 16 + (t8 & 1) * 8 + rs;
            int ch = ks * 2 + (t8 >> 1);
            uint32_t sw = (uint32_t)(rowA * 128) + (uint32_t)((ch ^ (rowA & 7)) << 4);
            ldsm4(ah[mf], dbuf + 0 * TILE_B + sw);
            ldsm4(al[mf], dbuf + 1 * TILE_B + sw);
        }
#pragma unroll
        for (int nbp = 0; nbp < 2; nbp++) {
            int rowB = nc + nbp * 16 + (t8 >> 1) * 8 + rs;
            int ch = ks * 2 + (t8 & 1);
            uint32_t sw = (uint32_t)(rowB * 128) + (uint32_t)((ch ^ (rowB & 7)) << 4);
            ldsm4(bh[nbp], dbuf + 2 * TILE_B + sw);
            ldsm4(bl[nbp], dbuf + 3 * TILE_B + sw);
        }
        // term-major issue: 8 distinct accumulators between any dd reuse
#pragma unroll
        for (int mf = 0; mf < 2; mf++)
#pragma unroll
            for (int nbp = 0; nbp < 2; nbp++)
#pragma unroll
                for (int nbi = 0; nbi < 2; nbi++)
                    mma_bf16(d[mf][nbp * 2 + nbi], ah[mf],
                             bh[nbp][2 * nbi], bh[nbp][2 * nbi + 1]);
#pragma unroll
        for (int mf = 0; mf < 2; mf++)
#pragma unroll
            for (int nbp = 0; nbp < 2; nbp++)
#pragma unroll
                for (int nbi = 0; nbi < 2; nbi++)
                    mma_bf16(d[mf][nbp * 2 + nbi], ah[mf],
                             bl[nbp][2 * nbi], bl[nbp][2 * nbi + 1]);
#pragma unroll
        for (int mf = 0; mf < 2; mf++)
#pragma unroll
            for (int nbp = 0; nbp < 2; nbp++)
#pragma unroll
                for (int nbi = 0; nbi < 2; nbi++)
                    mma_bf16(d[mf][nbp * 2 + nbi], al[mf],
                             bh[nbp][2 * nbi], bh[nbp][2 * nbi + 1]);
    }

    const float4* meta_i = (const float4*)(dbufp + 4 * TILE_B);
    const float4* meta_j = meta_i + 128;

    float sqr[4], rur[4];
    int labr[4], rloc4[4];
#pragma unroll
    for (int f = 0; f < 4; f++) {
        int rloc = mr + (f >> 1) * 16 + (f & 1) * 8 + (lane >> 2);
        rloc4[f] = rloc;
        float4 m = meta_i[rloc];
        sqr[f] = m.x; rur[f] = 2.0f * m.y; labr[f] = __float_as_int(m.z);
    }
    float rse[4], rpr[4];
    int rct[4];
#pragma unroll
    for (int f = 0; f < 4; f++) { rse[f] = 0.f; rpr[f] = 1.f; rct[f] = 0; }

#pragma unroll
    for (int nb = 0; nb < 4; nb++) {
#pragma unroll
        for (int ki = 0; ki < 2; ki++) {
            int cloc = nc + nb * 8 + (lane & 3) * 2 + ki;
            float4 mj = meta_j[cloc];
            int lj = __float_as_int(mj.z);
            float cse = 0.f, cpr = 1.f;
            int cct = 0;
#pragma unroll
            for (int f = 0; f < 4; f++) {
                float dot = d[f >> 1][nb][(f & 1) * 2 + ki];
                float sqd = fmaxf(fmaf(-2.0f, dot, sqr[f] + mj.x), 0.f);
                float z = fmaf(sqd * rur[f], mj.y, 1.0f);   // z >= 1 (sqd >= 0)
                float s = fast_sqrt(fmaf(z, z, -1.0f));
                // rv = exp(-d) = z - sqrt(z^2-1)  (== 1/(z+s); one MUFU)
                // clamp: true min rv ~2.8e-3, never binds; kills any NaN path
                float rv = fmaxf(z - s, 1e-6f);
                bool pos;
                float rve;
                if (DIAG) {
                    bool offd = (rloc4[f] != cloc);
                    pos = offd && (labr[f] == lj);
                    rve = offd ? rv : 0.f;
                } else {
                    pos = (labr[f] == lj);
                    rve = rv;
                }
                float rvp = pos ? rv : 1.f;
                rse[f] += rve; rpr[f] *= rvp; rct[f] += pos;
                cse += rve; cpr *= rvp; cct += pos;
            }
            // col-side inline reduce over lane>>2 (skip on diagonal pairs)
            if (!DIAG) {
                float csl = __log2f(cpr);
                cse += __shfl_xor_sync(0xffffffffu, cse, 4);
                csl += __shfl_xor_sync(0xffffffffu, csl, 4);
                cct += __shfl_xor_sync(0xffffffffu, cct, 4);
                cse += __shfl_xor_sync(0xffffffffu, cse, 8);
                csl += __shfl_xor_sync(0xffffffffu, csl, 8);
                cct += __shfl_xor_sync(0xffffffffu, cct, 8);
                cse += __shfl_xor_sync(0xffffffffu, cse, 16);
                csl += __shfl_xor_sync(0xffffffffu, csl, 16);
                cct += __shfl_xor_sync(0xffffffffu, cct, 16);
                if (lane < 4) {
                    int cstore = nc + nb * 8 + lane * 2 + ki;
                    int slot = (ti * NQ + wr) * N_PTS + (j0 + cstore);
                    g_pse[slot] = cse;
                    g_psl[slot] = csl * 0.69314718055994531f;
                    g_pct[slot] = cct;
                }
            }
        }
    }

    // row-side: reduce over lane&3; products <=8 factors (>=~6e-21), no renorm
#pragma unroll
    for (int f = 0; f < 4; f++) {
        float se = rse[f];
        float sl = __log2f(rpr[f]);
        int ct = rct[f];
        se += __shfl_xor_sync(0xffffffffu, se, 1);
        sl += __shfl_xor_sync(0xffffffffu, sl, 1);
        ct += __shfl_xor_sync(0xffffffffu, ct, 1);
        se += __shfl_xor_sync(0xffffffffu, se, 2);
        sl += __shfl_xor_sync(0xffffffffu, sl, 2);
        ct += __shfl_xor_sync(0xffffffffu, ct, 2);
        if ((lane & 3) == 0) {
            int slot = (tj * NQ + wc) * N_PTS + (i0 + rloc4[f]);
            g_pse[slot] = se;
            g_psl[slot] = sl * 0.69314718055994531f;
            g_pct[slot] = ct;
        }
    }
}

// ---- main: persistent double-buffered HMMA pipeline (R9 structure) ----
__global__ __launch_bounds__(NTHREADS, 1)
void main_kernel() {
    extern __shared__ __align__(16) char dsm_raw[];
    uint32_t dsm0 = smem_u32(dsm_raw);
    uint32_t dsm = (dsm0 + 127u) & ~127u;
    char* dsmp = dsm_raw + (dsm - dsm0);

    int tid = threadIdx.x;
    int w = tid >> 5, lane = tid & 31;
    int wr = w & 3, wc = w >> 2;

    int p = blockIdx.x;
    int ti = 0, tj = 0;
    if (p < NPAIR) {
        decode_pair(p, ti, tj);
        prefetch_pair(dsm, ti * BM, tj * BM, tid);
    }
    CP_COMMIT();

    int it = 0;
    for (; p < NPAIR; p += GRID, it++) {
        uint32_t dbuf = dsm + (uint32_t)(it & 1) * BUF_B;
        const char* dbufp = dsmp + (it & 1) * BUF_B;

        int tin = 0, tjn = 0;
        int pn = p + GRID;
        if (pn < NPAIR) {
            decode_pair(pn, tin, tjn);
            prefetch_pair(dsm + (uint32_t)((it + 1) & 1) * BUF_B,
                          tin * BM, tjn * BM, tid);
        }
        CP_COMMIT();
        CP_WAIT1();
        __syncthreads();

        if (ti == tj)
            compute_pair<true>(dbuf, dbufp, ti, tj, ti * BM, tj * BM, lane, wr, wc);
        else
            compute_pair<false>(dbuf, dbufp, ti, tj, ti * BM, tj * BM, lane, wr, wc);
        __syncthreads();

        ti = tin; tj = tjn;
    }
}

__global__ void rowred_kernel() {
    int i = blockIdx.x * blockDim.x + threadIdx.x;
    if (i >= N_PTS) return;
    float se = 0.f, sl = 0.f;
    int ct = 0;
#pragma unroll 8
    for (int t = 0; t < NQ * NT; t++) {
        se += g_pse[t * N_PTS + i];
        sl += g_psl[t * N_PTS + i];
        ct += g_pct[t * N_PTS + i];
    }
    float logA = __logf(fmaxf(se, 1e-30f));
    float P = (float)(ct > 0 ? ct : 1);
    g_rowloss[i] = logA - sl / P;
}

__global__ void final_kernel(float* __restrict__ out) {
    __shared__ float red[256];
    int t = threadIdx.x;
    float acc = 0.f;
#pragma unroll
    for (int it = 0; it < N_PTS / 256; it++)
        acc += g_rowloss[t + it * 256];
    red[t] = acc;
    __syncthreads();
    for (int s = 128; s > 0; s >>= 1) {
        if (t < s) red[t] += red[t + s];
        __syncthreads();
    }
    if (t == 0) out[0] = red[0];
}

extern "C" void kernel_launch(void* const* d_in, const int* in_sizes, int n_in,
                              void* d_out, int out_size) {
    const float* pts = (const float*)d_in[0];
    const long long* labs = (const long long*)d_in[1];
    cudaFuncSetAttribute(main_kernel, cudaFuncAttributeMaxDynamicSharedMemorySize,
                         2 * BUF_B + 128);
    prep_kernel<<<N_PTS / 256, 256>>>(pts, labs);
    main_kernel<<<GRID, NTHREADS, 2 * BUF_B + 128>>>();
    rowred_kernel<<<N_PTS / 256, 256>>>();
    final_kernel<<<1, 256>>>((float*)d_out);
}

// round 14
// speedup vs baseline: 1.4451x; 1.1636x over previous
#include <cuda_runtime.h>
#include <cuda_bf16.h>
#include <cstdint>

#define N_PTS 8192
#define DIM 64
#define BM 128
#define NT (N_PTS / BM)            // 64 tiles per side
#define NPAIR (NT * (NT + 1) / 2)  // 2080 tile pairs
#define NTHREADS 512
#define TILE_B 16384               // 128 rows x 64 bf16 (128B rows)
#define NQ 4                       // partial quarters per tile side
#define GRID 152                   // persistent CTAs
#define BUF_B (4 * TILE_B + 4096)  // 4 tiles + 256 float4 metadata
#define NCLS 16

// ---- scratch (device globals; all writes idempotent, replay-safe) ----
__device__ __align__(16) __nv_bfloat16 g_xhi[N_PTS * DIM];
__device__ __align__(16) __nv_bfloat16 g_xlo[N_PTS * DIM];
__device__ __align__(16) float4 g_meta[N_PTS];   // (sq, ru, lab_bits, 0)
__device__ float g_pse[NQ * NT * N_PTS];
__device__ float g_psl[NQ * NT * N_PTS];
__device__ float g_rowloss[N_PTS];

__device__ __forceinline__ uint32_t smem_u32(const void* p) {
    uint32_t a;
    asm("{ .reg .u64 t; cvta.to.shared.u64 t, %1; cvt.u32.u64 %0, t; }" : "=r"(a) : "l"(p));
    return a;
}
__device__ __forceinline__ float fast_sqrt(float x) {
    float r; asm("sqrt.approx.f32 %0, %1;" : "=f"(r) : "f"(x)); return r;
}
__device__ __forceinline__ void ldsm4(uint32_t* r, uint32_t addr) {
    asm volatile("ldmatrix.sync.aligned.m8n8.x4.shared.b16 {%0,%1,%2,%3}, [%4];"
                 : "=r"(r[0]), "=r"(r[1]), "=r"(r[2]), "=r"(r[3]) : "r"(addr));
}
__device__ __forceinline__ void mma_bf16(float* d, const uint32_t* a,
                                         uint32_t b0, uint32_t b1) {
    asm("mma.sync.aligned.m16n8k16.row.col.f32.bf16.bf16.f32 "
        "{%0,%1,%2,%3}, {%4,%5,%6,%7}, {%8,%9}, {%0,%1,%2,%3};"
        : "+f"(d[0]), "+f"(d[1]), "+f"(d[2]), "+f"(d[3])
        : "r"(a[0]), "r"(a[1]), "r"(a[2]), "r"(a[3]), "r"(b0), "r"(b1));
}
__device__ __forceinline__ void cp16(uint32_t dst, const void* src) {
    asm volatile("cp.async.cg.shared.global [%0], [%1], 16;" :: "r"(dst), "l"(src));
}
#define CP_COMMIT() asm volatile("cp.async.commit_group;" ::: "memory")
#define CP_WAIT1()  asm volatile("cp.async.wait_group 1;" ::: "memory")

__device__ __forceinline__ void decode_pair(int b, int& ti, int& tj) {
    int t = (int)floorf((129.0f - sqrtf(16641.0f - 8.0f * (float)b)) * 0.5f);
    if (t < 0) t = 0;
    if (t > NT - 1) t = NT - 1;
    while (t > 0 && b < t * (129 - t) / 2) t--;
    while (b >= (t + 1) * (128 - t) / 2) t++;
    ti = t;
    tj = t + (b - t * (129 - t) / 2);
}

// ---- prep ----
__global__ void prep_kernel(const float* __restrict__ pts,
                            const long long* __restrict__ labs) {
    int i = blockIdx.x * blockDim.x + threadIdx.x;
    if (i >= N_PTS) return;
    float s = 0.f;
#pragma unroll
    for (int q = 0; q < DIM; q++) {
        float x = pts[i * DIM + q];
        s = fmaf(x, x, s);
        __nv_bfloat16 hi = __float2bfloat16(x);
        __nv_bfloat16 lo = __float2bfloat16(x - __bfloat162float(hi));
        g_xhi[i * DIM + q] = hi;
        g_xlo[i * DIM + q] = lo;
    }
    float4 m;
    m.x = s;
    m.y = 1.0f / (1.0f - s);
    m.z = __int_as_float(((int)labs[i]) & (NCLS - 1));
    m.w = 0.f;
    g_meta[i] = m;
}

// ---- async prefetch of one pair's tiles + metadata into a smem buffer ----
__device__ __forceinline__ void prefetch_pair(uint32_t dbuf, int i0, int j0, int tid) {
    const uint4* HI = (const uint4*)g_xhi;
    const uint4* LO = (const uint4*)g_xlo;
#pragma unroll
    for (int it = 0; it < 8; it++) {
        int idx = tid + it * NTHREADS;              // 0..4095
        int tile = idx >> 10;                       // 0:Ah 1:Al 2:Bh 3:Bl
        int cidx = idx & 1023;
        int row = cidx >> 3, q = cidx & 7;
        int base = (tile & 2) ? j0 : i0;
        const uint4* src = (tile & 1) ? LO : HI;
        uint32_t off = (uint32_t)(row * 128) + (uint32_t)((q ^ (row & 7)) << 4);
        cp16(dbuf + tile * TILE_B + off, &src[(base + row) * 8 + q]);
    }
    if (tid < 256) {                                // 0..127: i rows, 128..255: j cols
        int g = ((tid >> 7) ? j0 : i0) + (tid & 127);
        cp16(dbuf + 4 * TILE_B + tid * 16, &g_meta[g]);
    }
}

// ---- one pair: GEMM (term-major) + dual-side epilogue (no count machinery) ----
template <bool DIAG>
__device__ __forceinline__ void compute_pair(uint32_t dbuf, const char* dbufp,
                                             int ti, int tj, int i0, int j0,
                                             int lane, int wr, int wc) {
    int mr = wr * 32, nc = wc * 32;
    int t8 = lane >> 3, rs = lane & 7;

    float d[2][4][4];
#pragma unroll
    for (int mf = 0; mf < 2; mf++)
#pragma unroll
        for (int nb = 0; nb < 4; nb++)
#pragma unroll
            for (int k = 0; k < 4; k++) d[mf][nb][k] = 0.f;

#pragma unroll
    for (int ks = 0; ks < 4; ks++) {
        uint32_t ah[2][4], al[2][4], bh[2][4], bl[2][4];
#pragma unroll
        for (int mf = 0; mf < 2; mf++) {
            int rowA = mr + mf * 16 + (t8 & 1) * 8 + rs;
            int ch = ks * 2 + (t8 >> 1);
            uint32_t sw = (uint32_t)(rowA * 128) + (uint32_t)((ch ^ (rowA & 7)) << 4);
            ldsm4(ah[mf], dbuf + 0 * TILE_B + sw);
            ldsm4(al[mf], dbuf + 1 * TILE_B + sw);
        }
#pragma unroll
        for (int nbp = 0; nbp < 2; nbp++) {
            int rowB = nc + nbp * 16 + (t8 >> 1) * 8 + rs;
            int ch = ks * 2 + (t8 & 1);
            uint32_t sw = (uint32_t)(rowB * 128) + (uint32_t)((ch ^ (rowB & 7)) << 4);
            ldsm4(bh[nbp], dbuf + 2 * TILE_B + sw);
            ldsm4(bl[nbp], dbuf + 3 * TILE_B + sw);
        }
        // term-major issue: 8 distinct accumulators between any dd reuse
#pragma unroll
        for (int mf = 0; mf < 2; mf++)
#pragma unroll
            for (int nbp = 0; nbp < 2; nbp++)
#pragma unroll
                for (int nbi = 0; nbi < 2; nbi++)
                    mma_bf16(d[mf][nbp * 2 + nbi], ah[mf],
                             bh[nbp][2 * nbi], bh[nbp][2 * nbi + 1]);
#pragma unroll
        for (int mf = 0; mf < 2; mf++)
#pragma unroll
            for (int nbp = 0; nbp < 2; nbp++)
#pragma unroll
                for (int nbi = 0; nbi < 2; nbi++)
                    mma_bf16(d[mf][nbp * 2 + nbi], ah[mf],
                             bl[nbp][2 * nbi], bl[nbp][2 * nbi + 1]);
#pragma unroll
        for (int mf = 0; mf < 2; mf++)
#pragma unroll
            for (int nbp = 0; nbp < 2; nbp++)
#pragma unroll
                for (int nbi = 0; nbi < 2; nbi++)
                    mma_bf16(d[mf][nbp * 2 + nbi], al[mf],
                             bh[nbp][2 * nbi], bh[nbp][2 * nbi + 1]);
    }

    const float4* meta_i = (const float4*)(dbufp + 4 * TILE_B);
    const float4* meta_j = meta_i + 128;

    float sqr[4], rur[4];
    int labr[4], rloc4[4];
#pragma unroll
    for (int f = 0; f < 4; f++) {
        int rloc = mr + (f >> 1) * 16 + (f & 1) * 8 + (lane >> 2);
        rloc4[f] = rloc;
        float4 m = meta_i[rloc];
        sqr[f] = m.x; rur[f] = 2.0f * m.y; labr[f] = __float_as_int(m.z);
    }
    float rse[4], rpr[4];
#pragma unroll
    for (int f = 0; f < 4; f++) { rse[f] = 0.f; rpr[f] = 1.f; }

#pragma unroll
    for (int nb = 0; nb < 4; nb++) {
#pragma unroll
        for (int ki = 0; ki < 2; ki++) {
            int cloc = nc + nb * 8 + (lane & 3) * 2 + ki;
            float4 mj = meta_j[cloc];
            int lj = __float_as_int(mj.z);
            float cse = 0.f, cpr = 1.f;
#pragma unroll
            for (int f = 0; f < 4; f++) {
                float dot = d[f >> 1][nb][(f & 1) * 2 + ki];
                float sqd = fmaxf(fmaf(-2.0f, dot, sqr[f] + mj.x), 0.f);
                float z = fmaf(sqd * rur[f], mj.y, 1.0f);   // z >= 1
                float s = fast_sqrt(fmaf(z, z, -1.0f));
                float rv = fmaxf(z - s, 1e-6f);      // exp(-d), one MUFU
                bool pos;
                float rve;
                if (DIAG) {
                    bool offd = (rloc4[f] != cloc);
                    pos = offd && (labr[f] == lj);
                    rve = offd ? rv : 0.f;
                } else {
                    pos = (labr[f] == lj);
                    rve = rv;
                }
                float rvp = pos ? rv : 1.f;
                rse[f] += rve; rpr[f] *= rvp;
                cse += rve; cpr *= rvp;
            }
            // col-side inline reduce over lane>>2 (skip on diagonal pairs)
            if (!DIAG) {
                float csl = __log2f(cpr);
                cse += __shfl_xor_sync(0xffffffffu, cse, 4);
                csl += __shfl_xor_sync(0xffffffffu, csl, 4);
                cse += __shfl_xor_sync(0xffffffffu, cse, 8);
                csl += __shfl_xor_sync(0xffffffffu, csl, 8);
                cse += __shfl_xor_sync(0xffffffffu, cse, 16);
                csl += __shfl_xor_sync(0xffffffffu, csl, 16);
                if (lane < 4) {
                    int cstore = nc + nb * 8 + lane * 2 + ki;
                    int slot = (ti * NQ + wr) * N_PTS + (j0 + cstore);
                    g_pse[slot] = cse;
                    g_psl[slot] = csl * 0.69314718055994531f;
                }
            }
        }
    }

    // row-side: reduce over lane&3; products <=8 factors (>=~6e-21), no renorm
#pragma unroll
    for (int f = 0; f < 4; f++) {
        float se = rse[f];
        float sl = __log2f(rpr[f]);
        se += __shfl_xor_sync(0xffffffffu, se, 1);
        sl += __shfl_xor_sync(0xffffffffu, sl, 1);
        se += __shfl_xor_sync(0xffffffffu, se, 2);
        sl += __shfl_xor_sync(0xffffffffu, sl, 2);
        if ((lane & 3) == 0) {
            int slot = (tj * NQ + wc) * N_PTS + (i0 + rloc4[f]);
            g_pse[slot] = se;
            g_psl[slot] = sl * 0.69314718055994531f;
        }
    }
}

// ---- main: persistent double-buffered HMMA pipeline (R9 structure) ----
__global__ __launch_bounds__(NTHREADS, 1)
void main_kernel() {
    extern __shared__ __align__(16) char dsm_raw[];
    uint32_t dsm0 = smem_u32(dsm_raw);
    uint32_t dsm = (dsm0 + 127u) & ~127u;
    char* dsmp = dsm_raw + (dsm - dsm0);

    int tid = threadIdx.x;
    int w = tid >> 5, lane = tid & 31;
    int wr = w & 3, wc = w >> 2;

    int p = blockIdx.x;
    int ti = 0, tj = 0;
    if (p < NPAIR) {
        decode_pair(p, ti, tj);
        prefetch_pair(dsm, ti * BM, tj * BM, tid);
    }
    CP_COMMIT();

    int it = 0;
    for (; p < NPAIR; p += GRID, it++) {
        uint32_t dbuf = dsm + (uint32_t)(it & 1) * BUF_B;
        const char* dbufp = dsmp + (it & 1) * BUF_B;

        int tin = 0, tjn = 0;
        int pn = p + GRID;
        if (pn < NPAIR) {
            decode_pair(pn, tin, tjn);
            prefetch_pair(dsm + (uint32_t)((it + 1) & 1) * BUF_B,
                          tin * BM, tjn * BM, tid);
        }
        CP_COMMIT();
        CP_WAIT1();
        __syncthreads();

        if (ti == tj)
            compute_pair<true>(dbuf, dbufp, ti, tj, ti * BM, tj * BM, lane, wr, wc);
        else
            compute_pair<false>(dbuf, dbufp, ti, tj, ti * BM, tj * BM, lane, wr, wc);
        __syncthreads();

        ti = tin; tj = tjn;
    }
}

// ---- rowred: label histogram (masked index; smem int atomics = deterministic),
//      then fold the 256 partial slots per row ----
__global__ void rowred_kernel() {
    __shared__ int hist[NCLS];
    int t = threadIdx.x;
    if (t < NCLS) hist[t] = 0;
    __syncthreads();
    for (int k = t; k < N_PTS; k += 256)
        atomicAdd(&hist[__float_as_int(g_meta[k].z) & (NCLS - 1)], 1);
    __syncthreads();

    int i = blockIdx.x * blockDim.x + t;
    if (i >= N_PTS) return;
    float se = 0.f, sl = 0.f;
#pragma unroll 8
    for (int q = 0; q < NQ * NT; q++) {
        se += g_pse[q * N_PTS + i];
        sl += g_psl[q * N_PTS + i];
    }
    int lab = __float_as_int(g_meta[i].z) & (NCLS - 1);
    int P = hist[lab] - 1;
    float logA = __logf(fmaxf(se, 1e-30f));
    g_rowloss[i] = logA - sl / (float)(P > 0 ? P : 1);
}

__global__ void final_kernel(float* __restrict__ out) {
    __shared__ float red[256];
    int t = threadIdx.x;
    float acc = 0.f;
#pragma unroll
    for (int it = 0; it < N_PTS / 256; it++)
        acc += g_rowloss[t + it * 256];
    red[t] = acc;
    __syncthreads();
    for (int s = 128; s > 0; s >>= 1) {
        if (t < s) red[t] += red[t + s];
        __syncthreads();
    }
    if (t == 0) out[0] = red[0];
}

extern "C" void kernel_launch(void* const* d_in, const int* in_sizes, int n_in,
                              void* d_out, int out_size) {
    const float* pts = (const float*)d_in[0];
    const long long* labs = (const long long*)d_in[1];
    cudaFuncSetAttribute(main_kernel, cudaFuncAttributeMaxDynamicSharedMemorySize,
                         2 * BUF_B + 128);
    prep_kernel<<<N_PTS / 256, 256>>>(pts, labs);
    main_kernel<<<GRID, NTHREADS, 2 * BUF_B + 128>>>();
    rowred_kernel<<<N_PTS / 256, 256>>>();
    final_kernel<<<1, 256>>>((float*)d_out);
}